// round 5
// baseline (speedup 1.0000x reference)
#include <cuda_runtime.h>
#include <cuda_bf16.h>
#include <cstdint>

// Problem constants
#define BB 2
#define SS 2048
#define EE 512
#define HH 8
#define DD 64
#define NEGV (-1e10f)

typedef unsigned long long ull;

// ---------------- packed f32x2 helpers (sm_103a FFMA2) ----------------
__device__ __forceinline__ ull fma2(ull a, ull b, ull c) {
    ull d;
    asm("fma.rn.f32x2 %0, %1, %2, %3;" : "=l"(d) : "l"(a), "l"(b), "l"(c));
    return d;
}
__device__ __forceinline__ ull mul2(ull a, ull b) {
    ull d;
    asm("mul.rn.f32x2 %0, %1, %2;" : "=l"(d) : "l"(a), "l"(b));
    return d;
}
__device__ __forceinline__ ull add2(ull a, ull b) {
    ull d;
    asm("add.rn.f32x2 %0, %1, %2;" : "=l"(d) : "l"(a), "l"(b));
    return d;
}
__device__ __forceinline__ ull pack2(float x, float y) {
    ull d;
    asm("mov.b64 %0, {%1, %2};" : "=l"(d) : "f"(x), "f"(y));
    return d;
}
__device__ __forceinline__ float2 unpack2(ull v) {
    float2 r;
    asm("mov.b64 {%0, %1}, %2;" : "=f"(r.x), "=f"(r.y) : "l"(v));
    return r;
}

// ---------------- scratch (no cudaMalloc allowed) ----------------
__device__ float g_Q[(size_t)BB * SS * EE];    // projected queries (B,S,H*D)
__device__ float g_AO[(size_t)BB * SS * EE];   // attention output  (B,S,H*D)
__device__ unsigned char g_maskB[(size_t)BB * SS * SS];  // canonical byte mask
__device__ int g_maskKind;                     // 0=uint8, 1=int32, 2=float32

// ---------------- mask dtype detection ----------------
__global__ void detect_mask_kernel(const unsigned int* __restrict__ w)
{
    int i32ok = 1, f32ok = 1;
    for (int i = threadIdx.x; i < 16384; i += 256) {
        unsigned int v = w[i];
        if (v > 1u) i32ok = 0;
        if (v != 0u && v != 0x3F800000u) f32ok = 0;
    }
    i32ok = __syncthreads_and(i32ok);
    f32ok = __syncthreads_and(f32ok);
    if (threadIdx.x == 0) g_maskKind = i32ok ? 1 : (f32ok ? 2 : 0);
}

// canonicalize to bytes (8 elements per thread)
__global__ __launch_bounds__(256)
void convert_mask_kernel(const void* __restrict__ mask)
{
    size_t idx = ((size_t)blockIdx.x * 256 + threadIdx.x) * 8;
    int kind = g_maskKind;
    unsigned char o[8];
    if (kind == 0) {
        *(ull*)o = *(const ull*)((const unsigned char*)mask + idx);
        #pragma unroll
        for (int i = 0; i < 8; ++i) o[i] = o[i] ? 1 : 0;
    } else if (kind == 1) {
        const int4* p = (const int4*)((const int*)mask + idx);
        int4 a = p[0], b = p[1];
        o[0] = a.x != 0; o[1] = a.y != 0; o[2] = a.z != 0; o[3] = a.w != 0;
        o[4] = b.x != 0; o[5] = b.y != 0; o[6] = b.z != 0; o[7] = b.w != 0;
    } else {
        const float4* p = (const float4*)((const float*)mask + idx);
        float4 a = p[0], b = p[1];
        o[0] = a.x != 0.f; o[1] = a.y != 0.f; o[2] = a.z != 0.f; o[3] = a.w != 0.f;
        o[4] = b.x != 0.f; o[5] = b.y != 0.f; o[6] = b.z != 0.f; o[7] = b.w != 0.f;
    }
    *(ull*)&g_maskB[idx] = *(ull*)o;
}

// ---------------- GEMM: C[M x 512] = A[M x 512] * B[512 x 512] ----------------
__global__ __launch_bounds__(256)
void gemm512_kernel(const float* __restrict__ A, const float* __restrict__ Bm,
                    float* __restrict__ C)
{
    __shared__ __align__(16) float As[16][132];   // [k][m], padded
    __shared__ __align__(16) float Bs[16][64];    // [k][n]

    const int tid = threadIdx.x;
    const int tx = tid & 15;
    const int ty = tid >> 4;
    const int mbase = blockIdx.x * 128;
    const int nbase = blockIdx.y * 64;

    ull c2[4][4];
    #pragma unroll
    for (int i = 0; i < 4; ++i)
        #pragma unroll
        for (int j = 0; j < 4; ++j) c2[i][j] = 0ull;

    const int arow0 = tid >> 2;
    const int acol  = (tid & 3) * 4;
    const int brow  = tid >> 4;
    const int bcol  = (tid & 15) * 4;

    for (int kk = 0; kk < 512; kk += 16) {
        #pragma unroll
        for (int p = 0; p < 2; ++p) {
            int row = arow0 + p * 64;
            float4 av = *(const float4*)(A + (size_t)(mbase + row) * 512 + kk + acol);
            As[acol + 0][row] = av.x;
            As[acol + 1][row] = av.y;
            As[acol + 2][row] = av.z;
            As[acol + 3][row] = av.w;
        }
        *(float4*)&Bs[brow][bcol] =
            *(const float4*)(Bm + (size_t)(kk + brow) * 512 + nbase + bcol);
        __syncthreads();

        #pragma unroll
        for (int k = 0; k < 16; ++k) {
            ulonglong2 a01 = *(const ulonglong2*)&As[k][ty * 8];
            ulonglong2 a23 = *(const ulonglong2*)&As[k][ty * 8 + 4];
            ull a2[4] = {a01.x, a01.y, a23.x, a23.y};
            float4 bv = *(const float4*)&Bs[k][tx * 4];
            ull bb0 = pack2(bv.x, bv.x);
            ull bb1 = pack2(bv.y, bv.y);
            ull bb2 = pack2(bv.z, bv.z);
            ull bb3 = pack2(bv.w, bv.w);
            #pragma unroll
            for (int i = 0; i < 4; ++i) {
                c2[i][0] = fma2(a2[i], bb0, c2[i][0]);
                c2[i][1] = fma2(a2[i], bb1, c2[i][1]);
                c2[i][2] = fma2(a2[i], bb2, c2[i][2]);
                c2[i][3] = fma2(a2[i], bb3, c2[i][3]);
            }
        }
        __syncthreads();
    }

    #pragma unroll
    for (int i = 0; i < 4; ++i) {
        float2 r0 = unpack2(c2[i][0]);
        float2 r1 = unpack2(c2[i][1]);
        float2 r2 = unpack2(c2[i][2]);
        float2 r3 = unpack2(c2[i][3]);
        int m0 = mbase + ty * 8 + 2 * i;
        float4 lo = make_float4(r0.x, r1.x, r2.x, r3.x);
        float4 hi = make_float4(r0.y, r1.y, r2.y, r3.y);
        *(float4*)(C + (size_t)m0 * 512 + nbase + tx * 4) = lo;
        *(float4*)(C + (size_t)(m0 + 1) * 512 + nbase + tx * 4) = hi;
    }
}

// ---------------- flash attention, fp32 (f32x2 packed), split-D x 2-rows ----
// Thread = 2 query rows x half of D. Warp covers 32 q rows. Block (128 thr)
// covers 128 q rows. K/V tiles of 64 keys in smem with 16B half-interleave:
// source float c (=h*32+4i..) -> smem offset i*8 + h*4.
// One 16B LDS feeds 4 FFMA2 (2 rows x 2) -> LDS wavefronts halved vs FMA.
__global__ __launch_bounds__(128, 2)
void attn_kernel(const float* __restrict__ K, const float* __restrict__ V,
                 const unsigned char* __restrict__ mask,
                 const float* __restrict__ Q, float* __restrict__ O)
{
    const int b = blockIdx.z;
    const int h = blockIdx.y;
    const int lane = threadIdx.x & 31;
    const int warp = threadIdx.x >> 5;
    const int half = lane & 1;          // which half of D
    const int rp = lane >> 1;           // row pair index 0..15
    const int r0 = blockIdx.x * 128 + warp * 32 + rp * 2;  // rows r0, r0+1

    __shared__ __align__(16) float Ks[64 * 64];
    __shared__ __align__(16) float Vs[64 * 64];

    // load q: 2 rows x 32 floats (own half) = 2 x 16 ull
    ull q2[2][16];
    #pragma unroll
    for (int r = 0; r < 2; ++r) {
        const ulonglong2* qp = (const ulonglong2*)
            (Q + (size_t)(b * SS + r0 + r) * EE + h * DD + half * 32);
        #pragma unroll
        for (int i = 0; i < 8; ++i) {
            ulonglong2 t = qp[i];
            q2[r][2 * i] = t.x;
            q2[r][2 * i + 1] = t.y;
        }
    }

    ull o2[2][16];
    #pragma unroll
    for (int r = 0; r < 2; ++r)
        #pragma unroll
        for (int i = 0; i < 16; ++i) o2[r][i] = 0ull;
    float m0v = -1e30f, m1v = -1e30f, l0v = 0.f, l1v = 0.f;

    const unsigned char* mrow0 = mask + (size_t)(b * SS + r0) * SS;
    const unsigned char* mrow1 = mrow0 + SS;
    const float* kbase = K + (((size_t)b * SS) * HH + h) * DD;
    const float* vbase = V + (((size_t)b * SS) * HH + h) * DD;

    #pragma unroll 1
    for (int kt = 0; kt < SS; kt += 64) {
        __syncthreads();
        // cooperative load of K/V tile with half-interleave swizzle
        #pragma unroll
        for (int i = 0; i < 8; ++i) {
            int p = threadIdx.x + 128 * i;
            int row = p >> 4;
            int c = (p & 15) * 4;                 // source column (0,4,..,60)
            int dst = ((c & 31) >> 2) * 8 + (c >> 5) * 4;  // swizzled offset
            *(float4*)&Ks[row * 64 + dst] =
                *(const float4*)(kbase + (size_t)(kt + row) * (HH * DD) + c);
            *(float4*)&Vs[row * 64 + dst] =
                *(const float4*)(vbase + (size_t)(kt + row) * (HH * DD) + c);
        }
        __syncthreads();

        #pragma unroll 1
        for (int c0 = 0; c0 < 64; c0 += 16) {
            // mask words for both rows (16 keys each)
            ull mwa0 = *(const ull*)(mrow0 + kt + c0);
            ull mwa1 = *(const ull*)(mrow0 + kt + c0 + 8);
            ull mwb0 = *(const ull*)(mrow1 + kt + c0);
            ull mwb1 = *(const ull*)(mrow1 + kt + c0 + 8);

            float s0[16], s1[16];
            #pragma unroll
            for (int j = 0; j < 16; ++j) {
                const float* kr = &Ks[(c0 + j) * 64 + half * 4];
                ull a00 = 0, a01 = 0, a10 = 0, a11 = 0;
                #pragma unroll
                for (int i = 0; i < 8; ++i) {
                    ulonglong2 kv = *(const ulonglong2*)(kr + i * 8);
                    a00 = fma2(q2[0][2 * i], kv.x, a00);
                    a01 = fma2(q2[0][2 * i + 1], kv.y, a01);
                    a10 = fma2(q2[1][2 * i], kv.x, a10);
                    a11 = fma2(q2[1][2 * i + 1], kv.y, a11);
                }
                float2 f0 = unpack2(add2(a00, a01));
                float2 f1 = unpack2(add2(a10, a11));
                float d0 = f0.x + f0.y;
                float d1 = f1.x + f1.y;
                d0 += __shfl_xor_sync(0xffffffffu, d0, 1);
                d1 += __shfl_xor_sync(0xffffffffu, d1, 1);
                ull mb0 = (j < 8) ? (mwa0 >> (8 * j)) : (mwa1 >> (8 * (j - 8)));
                ull mb1 = (j < 8) ? (mwb0 >> (8 * j)) : (mwb1 >> (8 * (j - 8)));
                s0[j] = (mb0 & 0xffull) ? NEGV : d0 * 0.125f;
                s1[j] = (mb1 & 0xffull) ? NEGV : d1 * 0.125f;
            }

            // chunk max + rescale per row
            float mc0 = s0[0], mc1 = s1[0];
            #pragma unroll
            for (int j = 1; j < 16; ++j) {
                mc0 = fmaxf(mc0, s0[j]);
                mc1 = fmaxf(mc1, s1[j]);
            }
            float mn0 = fmaxf(m0v, mc0);
            float mn1 = fmaxf(m1v, mc1);
            float al0 = __expf(m0v - mn0);
            float al1 = __expf(m1v - mn1);
            m0v = mn0; m1v = mn1;
            l0v *= al0; l1v *= al1;
            ull a02 = pack2(al0, al0);
            ull a12 = pack2(al1, al1);
            #pragma unroll
            for (int i = 0; i < 16; ++i) {
                o2[0][i] = mul2(o2[0][i], a02);
                o2[1][i] = mul2(o2[1][i], a12);
            }
            // accumulate P*V
            #pragma unroll
            for (int j = 0; j < 16; ++j) {
                float p0 = __expf(s0[j] - m0v);
                float p1 = __expf(s1[j] - m1v);
                l0v += p0;
                l1v += p1;
                ull p02 = pack2(p0, p0);
                ull p12 = pack2(p1, p1);
                const float* vr = &Vs[(c0 + j) * 64 + half * 4];
                #pragma unroll
                for (int i = 0; i < 8; ++i) {
                    ulonglong2 vv = *(const ulonglong2*)(vr + i * 8);
                    o2[0][2 * i]     = fma2(p02, vv.x, o2[0][2 * i]);
                    o2[0][2 * i + 1] = fma2(p02, vv.y, o2[0][2 * i + 1]);
                    o2[1][2 * i]     = fma2(p12, vv.x, o2[1][2 * i]);
                    o2[1][2 * i + 1] = fma2(p12, vv.y, o2[1][2 * i + 1]);
                }
            }
        }
    }

    float inv0 = 1.0f / l0v;
    float inv1 = 1.0f / l1v;
    ull i02 = pack2(inv0, inv0);
    ull i12 = pack2(inv1, inv1);
    #pragma unroll
    for (int r = 0; r < 2; ++r) {
        float* op = O + (size_t)(b * SS + r0 + r) * EE + h * DD + half * 32;
        ull sc = r ? i12 : i02;
        #pragma unroll
        for (int i = 0; i < 8; ++i) {
            float2 fa = unpack2(mul2(o2[r][2 * i], sc));
            float2 fb = unpack2(mul2(o2[r][2 * i + 1], sc));
            *(float4*)(op + 4 * i) = make_float4(fa.x, fa.y, fb.x, fb.y);
        }
    }
}

// ---------------- launch ----------------
extern "C" void kernel_launch(void* const* d_in, const int* in_sizes, int n_in,
                              void* d_out, int out_size)
{
    const float* inputs = (const float*)d_in[0];          // (B,S,E)
    const float* keys = (const float*)d_in[1];            // (B,S,H,D)
    const float* values = (const float*)d_in[2];          // (B,S,H,D)
    const float* wq = (const float*)d_in[3];              // (E, H*D)
    const float* wo = (const float*)d_in[4];              // (H*D, E)
    const void* mask_raw = d_in[5];                       // (B,S,S) bool
    float* out = (float*)d_out;                           // (B,S,E)

    float* qbuf;
    float* aobuf;
    unsigned char* maskb;
    cudaGetSymbolAddress((void**)&qbuf, g_Q);
    cudaGetSymbolAddress((void**)&aobuf, g_AO);
    cudaGetSymbolAddress((void**)&maskb, g_maskB);

    detect_mask_kernel<<<1, 256>>>((const unsigned int*)mask_raw);
    convert_mask_kernel<<<(BB * SS * SS) / (256 * 8), 256>>>(mask_raw);

    dim3 ggrid(32, 8);
    gemm512_kernel<<<ggrid, 256>>>(inputs, wq, qbuf);
    attn_kernel<<<dim3(SS / 128, HH, BB), 128>>>(keys, values, maskb, qbuf, aobuf);
    gemm512_kernel<<<ggrid, 256>>>(aobuf, wo, out);
}

// round 7
// speedup vs baseline: 3.0204x; 3.0204x over previous
#include <cuda_runtime.h>
#include <cuda_bf16.h>
#include <cstdint>

#define BB 2
#define SS 2048
#define EE 512
#define HH 8
#define DD 64

typedef unsigned long long ull;

// ---------------- packed f32x2 helpers (for gemm512) ----------------
__device__ __forceinline__ ull fma2(ull a, ull b, ull c) {
    ull d; asm("fma.rn.f32x2 %0, %1, %2, %3;" : "=l"(d) : "l"(a), "l"(b), "l"(c)); return d;
}
__device__ __forceinline__ ull pack2(float x, float y) {
    ull d; asm("mov.b64 %0, {%1, %2};" : "=l"(d) : "f"(x), "f"(y)); return d;
}
__device__ __forceinline__ float2 unpack2(ull v) {
    float2 r; asm("mov.b64 {%0, %1}, %2;" : "=f"(r.x), "=f"(r.y) : "l"(v)); return r;
}

// ---------------- bf16 helpers ----------------
// pack {lo,hi} floats -> bf16x2 word (lo in low 16 bits)
__device__ __forceinline__ uint32_t cvt2(float lo, float hi) {
    uint32_t r; asm("cvt.rn.bf16x2.f32 %0, %1, %2;" : "=r"(r) : "f"(hi), "f"(lo)); return r;
}
__device__ __forceinline__ float lof(uint32_t w) { return __uint_as_float(w << 16); }
__device__ __forceinline__ float hif(uint32_t w) { return __uint_as_float(w & 0xffff0000u); }

__device__ __forceinline__ uint32_t smem_to_u32(const void* p) {
    uint32_t a; asm("{ .reg .u64 t; cvta.to.shared.u64 t, %1; cvt.u32.u64 %0, t; }" : "=r"(a) : "l"(p)); return a;
}

// ---------------- mma.sync + ldmatrix (baseline PTX, works on compute_103) --
__device__ __forceinline__ void mma_bf16(float* c, const uint32_t* a, uint32_t b0, uint32_t b1) {
    asm volatile("mma.sync.aligned.m16n8k16.row.col.f32.bf16.bf16.f32 "
        "{%0,%1,%2,%3}, {%4,%5,%6,%7}, {%8,%9}, {%0,%1,%2,%3};"
        : "+f"(c[0]), "+f"(c[1]), "+f"(c[2]), "+f"(c[3])
        : "r"(a[0]), "r"(a[1]), "r"(a[2]), "r"(a[3]), "r"(b0), "r"(b1));
}
__device__ __forceinline__ void ldsm_x4(uint32_t* r, uint32_t addr) {
    asm volatile("ldmatrix.sync.aligned.m8n8.x4.shared.b16 {%0,%1,%2,%3}, [%4];"
        : "=r"(r[0]), "=r"(r[1]), "=r"(r[2]), "=r"(r[3]) : "r"(addr));
}
__device__ __forceinline__ void ldsm_x4_t(uint32_t* r, uint32_t addr) {
    asm volatile("ldmatrix.sync.aligned.m8n8.x4.trans.shared.b16 {%0,%1,%2,%3}, [%4];"
        : "=r"(r[0]), "=r"(r[1]), "=r"(r[2]), "=r"(r[3]) : "r"(addr));
}

// ---------------- scratch ----------------
__device__ float g_Q[(size_t)BB * SS * EE];
__device__ float g_AO[(size_t)BB * SS * EE];
__device__ ull g_maskBits[(size_t)BB * SS * SS / 64];
__device__ int g_maskKind;

// ---------------- mask dtype detect + bitpack ----------------
__global__ void detect_mask_kernel(const unsigned int* __restrict__ w)
{
    int i32ok = 1, f32ok = 1;
    for (int i = threadIdx.x; i < 16384; i += 256) {
        unsigned int v = w[i];
        if (v > 1u) i32ok = 0;
        if (v != 0u && v != 0x3F800000u) f32ok = 0;
    }
    i32ok = __syncthreads_and(i32ok);
    f32ok = __syncthreads_and(f32ok);
    if (threadIdx.x == 0) g_maskKind = i32ok ? 1 : (f32ok ? 2 : 0);
}

__global__ __launch_bounds__(256)
void bitpack_mask_kernel(const void* __restrict__ mask)
{
    size_t u = (size_t)blockIdx.x * 256 + threadIdx.x;
    int kind = g_maskKind;
    ull bits = 0;
    if (kind == 1) {
        const int4* p = (const int4*)mask + u * 16;
        #pragma unroll
        for (int w = 0; w < 16; ++w) {
            int4 a = p[w];
            bits |= ((ull)(a.x != 0)) << (4 * w) | ((ull)(a.y != 0)) << (4 * w + 1) |
                    ((ull)(a.z != 0)) << (4 * w + 2) | ((ull)(a.w != 0)) << (4 * w + 3);
        }
    } else if (kind == 2) {
        const float4* p = (const float4*)mask + u * 16;
        #pragma unroll
        for (int w = 0; w < 16; ++w) {
            float4 a = p[w];
            bits |= ((ull)(a.x != 0.f)) << (4 * w) | ((ull)(a.y != 0.f)) << (4 * w + 1) |
                    ((ull)(a.z != 0.f)) << (4 * w + 2) | ((ull)(a.w != 0.f)) << (4 * w + 3);
        }
    } else {
        const ull* p = (const ull*)mask + u * 8;
        #pragma unroll
        for (int w = 0; w < 8; ++w) {
            ull v = p[w];
            #pragma unroll
            for (int b8 = 0; b8 < 8; ++b8)
                bits |= ((ull)(((v >> (8 * b8)) & 0xffull) != 0)) << (8 * w + b8);
        }
    }
    g_maskBits[u] = bits;
}

// ---------------- GEMM: C[M x 512] = A[M x 512] * B[512 x 512] -------------
__global__ __launch_bounds__(256)
void gemm512_kernel(const float* __restrict__ A, const float* __restrict__ Bm,
                    float* __restrict__ C)
{
    __shared__ __align__(16) float As[16][132];
    __shared__ __align__(16) float Bs[16][64];
    const int tid = threadIdx.x;
    const int tx = tid & 15, ty = tid >> 4;
    const int mbase = blockIdx.x * 128, nbase = blockIdx.y * 64;

    ull c2[4][4];
    #pragma unroll
    for (int i = 0; i < 4; ++i)
        #pragma unroll
        for (int j = 0; j < 4; ++j) c2[i][j] = 0ull;

    const int arow0 = tid >> 2, acol = (tid & 3) * 4;
    const int brow = tid >> 4, bcol = (tid & 15) * 4;

    for (int kk = 0; kk < 512; kk += 16) {
        #pragma unroll
        for (int p = 0; p < 2; ++p) {
            int row = arow0 + p * 64;
            float4 av = *(const float4*)(A + (size_t)(mbase + row) * 512 + kk + acol);
            As[acol + 0][row] = av.x; As[acol + 1][row] = av.y;
            As[acol + 2][row] = av.z; As[acol + 3][row] = av.w;
        }
        *(float4*)&Bs[brow][bcol] = *(const float4*)(Bm + (size_t)(kk + brow) * 512 + nbase + bcol);
        __syncthreads();
        #pragma unroll
        for (int k = 0; k < 16; ++k) {
            ulonglong2 a01 = *(const ulonglong2*)&As[k][ty * 8];
            ulonglong2 a23 = *(const ulonglong2*)&As[k][ty * 8 + 4];
            ull a2[4] = {a01.x, a01.y, a23.x, a23.y};
            float4 bv = *(const float4*)&Bs[k][tx * 4];
            ull bb0 = pack2(bv.x, bv.x), bb1 = pack2(bv.y, bv.y);
            ull bb2 = pack2(bv.z, bv.z), bb3 = pack2(bv.w, bv.w);
            #pragma unroll
            for (int i = 0; i < 4; ++i) {
                c2[i][0] = fma2(a2[i], bb0, c2[i][0]);
                c2[i][1] = fma2(a2[i], bb1, c2[i][1]);
                c2[i][2] = fma2(a2[i], bb2, c2[i][2]);
                c2[i][3] = fma2(a2[i], bb3, c2[i][3]);
            }
        }
        __syncthreads();
    }
    #pragma unroll
    for (int i = 0; i < 4; ++i) {
        float2 r0 = unpack2(c2[i][0]), r1 = unpack2(c2[i][1]);
        float2 r2 = unpack2(c2[i][2]), r3 = unpack2(c2[i][3]);
        int m0 = mbase + ty * 8 + 2 * i;
        *(float4*)(C + (size_t)m0 * 512 + nbase + tx * 4) = make_float4(r0.x, r1.x, r2.x, r3.x);
        *(float4*)(C + (size_t)(m0 + 1) * 512 + nbase + tx * 4) = make_float4(r0.y, r1.y, r2.y, r3.y);
    }
}

// ---------------- HMMA flash attention ----------------
// CTA = (b, h, 128 q rows); 4 warps x 32 rows. bf16 hi/lo 3-term splits.
#define LST 72   // smem row stride in bf16 elems (144B -> conflict-free ldmatrix)

__global__ __launch_bounds__(128, 2)
void attn_mma_kernel(const float* __restrict__ K, const float* __restrict__ V,
                     const ull* __restrict__ mbits,
                     const float* __restrict__ Q, float* __restrict__ O)
{
    __shared__ __align__(16) __nv_bfloat16 sKh[64 * LST], sKl[64 * LST];
    __shared__ __align__(16) __nv_bfloat16 sVh[64 * LST], sVl[64 * LST];

    const int b = blockIdx.z, h = blockIdx.y;
    const int qbase = blockIdx.x * 128;
    const int tid = threadIdx.x;
    const int warp = tid >> 5, lane = tid & 31;
    const int g = lane >> 3, lrow = lane & 7;

    // ---- stage Q (scaled by 1/8, hi/lo split): rows 0-63 in sK*, 64-127 in sV* ----
    {
        const float4* qr = (const float4*)(Q + (size_t)(b * SS + qbase + tid) * EE + h * DD);
        uint32_t* dh = (uint32_t*)((tid < 64 ? sKh : sVh) + (tid & 63) * LST);
        uint32_t* dl = (uint32_t*)((tid < 64 ? sKl : sVl) + (tid & 63) * LST);
        #pragma unroll
        for (int i = 0; i < 16; ++i) {
            float4 v = qr[i];
            v.x *= 0.125f; v.y *= 0.125f; v.z *= 0.125f; v.w *= 0.125f;
            uint32_t h0 = cvt2(v.x, v.y), h1 = cvt2(v.z, v.w);
            dh[2 * i] = h0; dh[2 * i + 1] = h1;
            dl[2 * i] = cvt2(v.x - lof(h0), v.y - hif(h0));
            dl[2 * i + 1] = cvt2(v.z - lof(h1), v.w - hif(h1));
        }
    }
    __syncthreads();

    // ---- load persistent Q A-fragments (hi/lo) ----
    uint32_t Qh[2][4][4], Ql[2][4][4];
    {
        const __nv_bfloat16* bh = (warp < 2) ? sKh : sVh;
        const __nv_bfloat16* bl = (warp < 2) ? sKl : sVl;
        const int rowbase = (warp & 1) * 32;
        // A non-trans x4: g0: rows0-7 k+0 | g1: rows8-15 k+0 | g2: rows0-7 k+8 | g3: rows8-15 k+8
        const int arow = rowbase + (g & 1) * 8 + lrow;
        const int acol = (g >> 1) * 8;
        #pragma unroll
        for (int i = 0; i < 2; ++i)
            #pragma unroll
            for (int kb = 0; kb < 4; ++kb) {
                ldsm_x4(Qh[i][kb], smem_to_u32(bh + (arow + i * 16) * LST + acol + kb * 16));
                ldsm_x4(Ql[i][kb], smem_to_u32(bl + (arow + i * 16) * LST + acol + kb * 16));
            }
    }
    __syncthreads();

    float Oa[2][8][4];
    #pragma unroll
    for (int i = 0; i < 2; ++i)
        #pragma unroll
        for (int j = 0; j < 8; ++j)
            #pragma unroll
            for (int r = 0; r < 4; ++r) Oa[i][j][r] = 0.f;
    float lsum[4] = {0.f, 0.f, 0.f, 0.f};

    // ldmatrix per-lane base offsets
    // K as B (non-trans): g0: keys0-7 d+0 | g1: keys0-7 d+8 | g2: keys8-15 d+0 | g3: keys8-15 d+8
    const uint32_t kOff = (uint32_t)(((g >> 1) * 8 + lrow) * LST + (g & 1) * 8) * 2;
    // V as B (trans):     g0: keys0-7 d+0 | g1: keys8-15 d+0 | g2: keys0-7 d+8 | g3: keys8-15 d+8
    const uint32_t vOff = (uint32_t)(((g & 1) * 8 + lrow) * LST + (g >> 1) * 8) * 2;
    const uint32_t uKh = smem_to_u32(sKh), uKl = smem_to_u32(sKl);
    const uint32_t uVh = smem_to_u32(sVh), uVl = smem_to_u32(sVl);

    const float* kbase = K + (((size_t)b * SS) * HH + h) * DD;
    const float* vbase = V + (((size_t)b * SS) * HH + h) * DD;
    const ull* mrow = mbits + (size_t)(b * SS + qbase + warp * 32) * (SS / 64);

    const int srow = tid >> 1;            // staging: key row
    const int sd0 = (tid & 1) * 32;       // staging: d half

    #pragma unroll 1
    for (int t = 0; t < SS / 64; ++t) {
        const int kt = t * 64;
        __syncthreads();
        // ---- stage K/V tile as bf16 hi/lo ----
        {
            const float4* kr = (const float4*)(kbase + (size_t)(kt + srow) * (HH * DD) + sd0);
            const float4* vr = (const float4*)(vbase + (size_t)(kt + srow) * (HH * DD) + sd0);
            uint32_t* kh = (uint32_t*)(sKh + srow * LST + sd0);
            uint32_t* kl = (uint32_t*)(sKl + srow * LST + sd0);
            uint32_t* vh = (uint32_t*)(sVh + srow * LST + sd0);
            uint32_t* vl = (uint32_t*)(sVl + srow * LST + sd0);
            #pragma unroll
            for (int i = 0; i < 8; ++i) {
                float4 a = kr[i];
                uint32_t h0 = cvt2(a.x, a.y), h1 = cvt2(a.z, a.w);
                kh[2 * i] = h0; kh[2 * i + 1] = h1;
                kl[2 * i] = cvt2(a.x - lof(h0), a.y - hif(h0));
                kl[2 * i + 1] = cvt2(a.z - lof(h1), a.w - hif(h1));
                float4 c = vr[i];
                uint32_t g0 = cvt2(c.x, c.y), g1 = cvt2(c.z, c.w);
                vh[2 * i] = g0; vh[2 * i + 1] = g1;
                vl[2 * i] = cvt2(c.x - lof(g0), c.y - hif(g0));
                vl[2 * i + 1] = cvt2(c.z - lof(g1), c.w - hif(g1));
            }
        }
        __syncthreads();

        // ---- S = Q K^T (3-term split) ----
        float S[2][8][4];
        #pragma unroll
        for (int i = 0; i < 2; ++i)
            #pragma unroll
            for (int j = 0; j < 8; ++j)
                #pragma unroll
                for (int r = 0; r < 4; ++r) S[i][j][r] = 0.f;

        #pragma unroll
        for (int np = 0; np < 4; ++np) {
            #pragma unroll
            for (int kb = 0; kb < 4; ++kb) {
                uint32_t Bh[4], Bl[4];
                uint32_t off = (uint32_t)(np * 16 * LST + kb * 16) * 2;
                ldsm_x4(Bh, uKh + off + kOff);
                ldsm_x4(Bl, uKl + off + kOff);
                #pragma unroll
                for (int i = 0; i < 2; ++i) {
                    mma_bf16(S[i][2 * np], Qh[i][kb], Bh[0], Bh[1]);
                    mma_bf16(S[i][2 * np], Qh[i][kb], Bl[0], Bl[1]);
                    mma_bf16(S[i][2 * np], Ql[i][kb], Bh[0], Bh[1]);
                    mma_bf16(S[i][2 * np + 1], Qh[i][kb], Bh[2], Bh[3]);
                    mma_bf16(S[i][2 * np + 1], Qh[i][kb], Bl[2], Bl[3]);
                    mma_bf16(S[i][2 * np + 1], Ql[i][kb], Bh[2], Bh[3]);
                }
            }
        }

        // ---- softmax (no max pass; masked -> 0) + pack P A-frags hi/lo ----
        uint32_t Ph[2][4][4], Pl[2][4][4];
        #pragma unroll
        for (int i = 0; i < 2; ++i) {
            ull mw0 = mrow[(size_t)(i * 16 + (lane >> 2)) * (SS / 64) + t];
            ull mw1 = mrow[(size_t)(i * 16 + 8 + (lane >> 2)) * (SS / 64) + t];
            #pragma unroll
            for (int nb = 0; nb < 8; ++nb) {
                int p0 = nb * 8 + (lane & 3) * 2;
                float e0 = ((mw0 >> p0) & 1ull) ? 0.f : __expf(S[i][nb][0]);
                float e1 = ((mw0 >> (p0 + 1)) & 1ull) ? 0.f : __expf(S[i][nb][1]);
                float e2 = ((mw1 >> p0) & 1ull) ? 0.f : __expf(S[i][nb][2]);
                float e3 = ((mw1 >> (p0 + 1)) & 1ull) ? 0.f : __expf(S[i][nb][3]);
                lsum[i * 2] += e0 + e1;
                lsum[i * 2 + 1] += e2 + e3;
                int kb = nb >> 1, sub = (nb & 1) * 2;
                uint32_t h01 = cvt2(e0, e1), h23 = cvt2(e2, e3);
                Ph[i][kb][sub] = h01;
                Ph[i][kb][sub + 1] = h23;
                Pl[i][kb][sub] = cvt2(e0 - lof(h01), e1 - hif(h01));
                Pl[i][kb][sub + 1] = cvt2(e2 - lof(h23), e3 - hif(h23));
            }
        }

        // ---- O += P V (3-term split), V frags via ldmatrix.trans ----
        #pragma unroll
        for (int dp = 0; dp < 4; ++dp) {
            #pragma unroll
            for (int kb = 0; kb < 4; ++kb) {
                uint32_t Bh[4], Bl[4];
                uint32_t off = (uint32_t)(kb * 16 * LST + dp * 16) * 2;
                ldsm_x4_t(Bh, uVh + off + vOff);
                ldsm_x4_t(Bl, uVl + off + vOff);
                #pragma unroll
                for (int i = 0; i < 2; ++i) {
                    mma_bf16(Oa[i][2 * dp], Ph[i][kb], Bh[0], Bh[1]);
                    mma_bf16(Oa[i][2 * dp], Ph[i][kb], Bl[0], Bl[1]);
                    mma_bf16(Oa[i][2 * dp], Pl[i][kb], Bh[0], Bh[1]);
                    mma_bf16(Oa[i][2 * dp + 1], Ph[i][kb], Bh[2], Bh[3]);
                    mma_bf16(Oa[i][2 * dp + 1], Ph[i][kb], Bl[2], Bl[3]);
                    mma_bf16(Oa[i][2 * dp + 1], Pl[i][kb], Bh[2], Bh[3]);
                }
            }
        }
    }

    // ---- normalize + store ----
    #pragma unroll
    for (int i = 0; i < 4; ++i) {
        lsum[i] += __shfl_xor_sync(0xffffffffu, lsum[i], 1);
        lsum[i] += __shfl_xor_sync(0xffffffffu, lsum[i], 2);
    }
    #pragma unroll
    for (int i = 0; i < 2; ++i) {
        float inv0 = 1.f / lsum[i * 2];
        float inv1 = 1.f / lsum[i * 2 + 1];
        int r0 = qbase + warp * 32 + i * 16 + (lane >> 2);
        float* o0 = O + (size_t)(b * SS + r0) * EE + h * DD;
        float* o1 = o0 + (size_t)8 * EE;
        #pragma unroll
        for (int nb = 0; nb < 8; ++nb) {
            int d = nb * 8 + (lane & 3) * 2;
            *(float2*)(o0 + d) = make_float2(Oa[i][nb][0] * inv0, Oa[i][nb][1] * inv0);
            *(float2*)(o1 + d) = make_float2(Oa[i][nb][2] * inv1, Oa[i][nb][3] * inv1);
        }
    }
}

// ---------------- launch ----------------
extern "C" void kernel_launch(void* const* d_in, const int* in_sizes, int n_in,
                              void* d_out, int out_size)
{
    const float* inputs = (const float*)d_in[0];
    const float* keys = (const float*)d_in[1];
    const float* values = (const float*)d_in[2];
    const float* wq = (const float*)d_in[3];
    const float* wo = (const float*)d_in[4];
    const void* mask_raw = d_in[5];
    float* out = (float*)d_out;

    float* qbuf; float* aobuf; ull* mbits;
    cudaGetSymbolAddress((void**)&qbuf, g_Q);
    cudaGetSymbolAddress((void**)&aobuf, g_AO);
    cudaGetSymbolAddress((void**)&mbits, g_maskBits);

    detect_mask_kernel<<<1, 256>>>((const unsigned int*)mask_raw);
    bitpack_mask_kernel<<<(BB * SS * SS / 64) / 256, 256>>>(mask_raw);

    dim3 ggrid(32, 8);
    gemm512_kernel<<<ggrid, 256>>>(inputs, wq, qbuf);
    attn_mma_kernel<<<dim3(SS / 128, HH, BB), 128>>>(keys, values, mbits, qbuf, aobuf);
    gemm512_kernel<<<ggrid, 256>>>(aobuf, wo, out);
}

// round 8
// speedup vs baseline: 3.4719x; 1.1495x over previous
#include <cuda_runtime.h>
#include <cuda_bf16.h>
#include <cstdint>

#define BB 2
#define SS 2048
#define EE 512
#define HH 8
#define DD 64

typedef unsigned long long ull;

// ---------------- bf16 helpers ----------------
// pack {lo,hi} floats -> bf16x2 word (lo in low 16 bits)
__device__ __forceinline__ uint32_t cvt2(float lo, float hi) {
    uint32_t r; asm("cvt.rn.bf16x2.f32 %0, %1, %2;" : "=r"(r) : "f"(hi), "f"(lo)); return r;
}
__device__ __forceinline__ float lof(uint32_t w) { return __uint_as_float(w << 16); }
__device__ __forceinline__ float hif(uint32_t w) { return __uint_as_float(w & 0xffff0000u); }

__device__ __forceinline__ uint32_t smem_to_u32(const void* p) {
    uint32_t a; asm("{ .reg .u64 t; cvta.to.shared.u64 t, %1; cvt.u32.u64 %0, t; }" : "=r"(a) : "l"(p)); return a;
}

// ---------------- mma.sync + ldmatrix (baseline PTX, OK on compute_103) ----
__device__ __forceinline__ void mma_bf16(float* c, const uint32_t* a, uint32_t b0, uint32_t b1) {
    asm volatile("mma.sync.aligned.m16n8k16.row.col.f32.bf16.bf16.f32 "
        "{%0,%1,%2,%3}, {%4,%5,%6,%7}, {%8,%9}, {%0,%1,%2,%3};"
        : "+f"(c[0]), "+f"(c[1]), "+f"(c[2]), "+f"(c[3])
        : "r"(a[0]), "r"(a[1]), "r"(a[2]), "r"(a[3]), "r"(b0), "r"(b1));
}
__device__ __forceinline__ void ldsm_x4(uint32_t* r, uint32_t addr) {
    asm volatile("ldmatrix.sync.aligned.m8n8.x4.shared.b16 {%0,%1,%2,%3}, [%4];"
        : "=r"(r[0]), "=r"(r[1]), "=r"(r[2]), "=r"(r[3]) : "r"(addr));
}
__device__ __forceinline__ void ldsm_x4_t(uint32_t* r, uint32_t addr) {
    asm volatile("ldmatrix.sync.aligned.m8n8.x4.trans.shared.b16 {%0,%1,%2,%3}, [%4];"
        : "=r"(r[0]), "=r"(r[1]), "=r"(r[2]), "=r"(r[3]) : "r"(addr));
}

// ---------------- scratch ----------------
__device__ float g_Q[(size_t)BB * SS * EE];
__device__ float g_AO[(size_t)BB * SS * EE];
__device__ ull g_maskBits[(size_t)BB * SS * SS / 64];
__device__ int g_maskKind;

// ---------------- mask dtype detect + bitpack ----------------
__global__ void detect_mask_kernel(const unsigned int* __restrict__ w)
{
    int i32ok = 1, f32ok = 1;
    for (int i = threadIdx.x; i < 16384; i += 256) {
        unsigned int v = w[i];
        if (v > 1u) i32ok = 0;
        if (v != 0u && v != 0x3F800000u) f32ok = 0;
    }
    i32ok = __syncthreads_and(i32ok);
    f32ok = __syncthreads_and(f32ok);
    if (threadIdx.x == 0) g_maskKind = i32ok ? 1 : (f32ok ? 2 : 0);
}

__global__ __launch_bounds__(256)
void bitpack_mask_kernel(const void* __restrict__ mask)
{
    size_t u = (size_t)blockIdx.x * 256 + threadIdx.x;
    int kind = g_maskKind;
    ull bits = 0;
    if (kind == 1) {
        const int4* p = (const int4*)mask + u * 16;
        #pragma unroll
        for (int w = 0; w < 16; ++w) {
            int4 a = p[w];
            bits |= ((ull)(a.x != 0)) << (4 * w) | ((ull)(a.y != 0)) << (4 * w + 1) |
                    ((ull)(a.z != 0)) << (4 * w + 2) | ((ull)(a.w != 0)) << (4 * w + 3);
        }
    } else if (kind == 2) {
        const float4* p = (const float4*)mask + u * 16;
        #pragma unroll
        for (int w = 0; w < 16; ++w) {
            float4 a = p[w];
            bits |= ((ull)(a.x != 0.f)) << (4 * w) | ((ull)(a.y != 0.f)) << (4 * w + 1) |
                    ((ull)(a.z != 0.f)) << (4 * w + 2) | ((ull)(a.w != 0.f)) << (4 * w + 3);
        }
    } else {
        const ull* p = (const ull*)mask + u * 8;
        #pragma unroll
        for (int w = 0; w < 8; ++w) {
            ull v = p[w];
            #pragma unroll
            for (int b8 = 0; b8 < 8; ++b8)
                bits |= ((ull)(((v >> (8 * b8)) & 0xffull) != 0)) << (8 * w + b8);
        }
    }
    g_maskBits[u] = bits;
}

// ---------------- HMMA GEMM: C[M x 512] = A[M x 512] * B[512 x 512] --------
// bf16 hi/lo 3-term split, k-chunks of 32, CTA tile 128x64, 4 warps.
#define GLA 40   // A smem row stride (32 k + 8 pad)  -> 80B rows, conflict-free
#define GLB 72   // B smem row stride (64 n + 8 pad)  -> 144B rows, conflict-free

__global__ __launch_bounds__(128, 2)
void gemm_mma_kernel(const float* __restrict__ A, const float* __restrict__ Bm,
                     float* __restrict__ C)
{
    __shared__ __align__(16) __nv_bfloat16 sAh[128 * GLA], sAl[128 * GLA];
    __shared__ __align__(16) __nv_bfloat16 sBh[32 * GLB], sBl[32 * GLB];

    const int tid = threadIdx.x;
    const int warp = tid >> 5, lane = tid & 31;
    const int g = lane >> 3, lrow = lane & 7;
    const int mbase = blockIdx.x * 128, nbase = blockIdx.y * 64;

    float Ca[2][8][4];
    #pragma unroll
    for (int i = 0; i < 2; ++i)
        #pragma unroll
        for (int j = 0; j < 8; ++j)
            #pragma unroll
            for (int r = 0; r < 4; ++r) Ca[i][j][r] = 0.f;

    const int arow = warp * 32 + (g & 1) * 8 + lrow;
    const int acol = (g >> 1) * 8;
    const uint32_t bOff = (uint32_t)(((g & 1) * 8 + lrow) * GLB + (g >> 1) * 8) * 2;
    const uint32_t uBh = smem_to_u32(sBh), uBl = smem_to_u32(sBl);

    #pragma unroll 1
    for (int kk = 0; kk < 512; kk += 32) {
        __syncthreads();
        // stage A chunk: row = tid, 32 cols, hi/lo split
        {
            const float4* ar = (const float4*)(A + (size_t)(mbase + tid) * 512 + kk);
            uint32_t* ah = (uint32_t*)(sAh + tid * GLA);
            uint32_t* al = (uint32_t*)(sAl + tid * GLA);
            #pragma unroll
            for (int i = 0; i < 8; ++i) {
                float4 v = ar[i];
                uint32_t h0 = cvt2(v.x, v.y), h1 = cvt2(v.z, v.w);
                ah[2 * i] = h0; ah[2 * i + 1] = h1;
                al[2 * i] = cvt2(v.x - lof(h0), v.y - hif(h0));
                al[2 * i + 1] = cvt2(v.z - lof(h1), v.w - hif(h1));
            }
        }
        // stage B chunk: row = tid>>2 (0..31), cols (tid&3)*16..+15
        {
            int br = tid >> 2, bc = (tid & 3) * 16;
            const float4* bp = (const float4*)(Bm + (size_t)(kk + br) * 512 + nbase + bc);
            uint32_t* bh = (uint32_t*)(sBh + br * GLB + bc);
            uint32_t* bl = (uint32_t*)(sBl + br * GLB + bc);
            #pragma unroll
            for (int i = 0; i < 4; ++i) {
                float4 v = bp[i];
                uint32_t h0 = cvt2(v.x, v.y), h1 = cvt2(v.z, v.w);
                bh[2 * i] = h0; bh[2 * i + 1] = h1;
                bl[2 * i] = cvt2(v.x - lof(h0), v.y - hif(h0));
                bl[2 * i + 1] = cvt2(v.z - lof(h1), v.w - hif(h1));
            }
        }
        __syncthreads();

        // A fragments for this chunk
        uint32_t Ah[2][2][4], Al[2][2][4];
        #pragma unroll
        for (int i = 0; i < 2; ++i)
            #pragma unroll
            for (int kb = 0; kb < 2; ++kb) {
                ldsm_x4(Ah[i][kb], smem_to_u32(sAh + (arow + i * 16) * GLA + acol + kb * 16));
                ldsm_x4(Al[i][kb], smem_to_u32(sAl + (arow + i * 16) * GLA + acol + kb * 16));
            }

        #pragma unroll
        for (int np = 0; np < 4; ++np) {
            #pragma unroll
            for (int kb = 0; kb < 2; ++kb) {
                uint32_t Bh[4], Bl[4];
                uint32_t off = (uint32_t)(kb * 16 * GLB + np * 16) * 2;
                ldsm_x4_t(Bh, uBh + off + bOff);
                ldsm_x4_t(Bl, uBl + off + bOff);
                // term-major ordering: spaces same-accumulator MMAs 4 apart
                #pragma unroll
                for (int i = 0; i < 2; ++i) mma_bf16(Ca[i][2 * np], Ah[i][kb], Bh[0], Bh[1]);
                #pragma unroll
                for (int i = 0; i < 2; ++i) mma_bf16(Ca[i][2 * np + 1], Ah[i][kb], Bh[2], Bh[3]);
                #pragma unroll
                for (int i = 0; i < 2; ++i) mma_bf16(Ca[i][2 * np], Ah[i][kb], Bl[0], Bl[1]);
                #pragma unroll
                for (int i = 0; i < 2; ++i) mma_bf16(Ca[i][2 * np + 1], Ah[i][kb], Bl[2], Bl[3]);
                #pragma unroll
                for (int i = 0; i < 2; ++i) mma_bf16(Ca[i][2 * np], Al[i][kb], Bh[0], Bh[1]);
                #pragma unroll
                for (int i = 0; i < 2; ++i) mma_bf16(Ca[i][2 * np + 1], Al[i][kb], Bh[2], Bh[3]);
            }
        }
    }

    // epilogue (same mapping as attn O store)
    #pragma unroll
    for (int i = 0; i < 2; ++i) {
        int r0 = mbase + warp * 32 + i * 16 + (lane >> 2);
        float* c0 = C + (size_t)r0 * 512 + nbase;
        float* c1 = c0 + (size_t)8 * 512;
        #pragma unroll
        for (int nb = 0; nb < 8; ++nb) {
            int d = nb * 8 + (lane & 3) * 2;
            *(float2*)(c0 + d) = make_float2(Ca[i][nb][0], Ca[i][nb][1]);
            *(float2*)(c1 + d) = make_float2(Ca[i][nb][2], Ca[i][nb][3]);
        }
    }
}

// ---------------- HMMA flash attention ----------------
#define LST 72   // smem row stride in bf16 elems (144B -> conflict-free ldmatrix)

__global__ __launch_bounds__(128, 2)
void attn_mma_kernel(const float* __restrict__ K, const float* __restrict__ V,
                     const ull* __restrict__ mbits,
                     const float* __restrict__ Q, float* __restrict__ O)
{
    __shared__ __align__(16) __nv_bfloat16 sKh[64 * LST], sKl[64 * LST];
    __shared__ __align__(16) __nv_bfloat16 sVh[64 * LST], sVl[64 * LST];

    const int b = blockIdx.z, h = blockIdx.y;
    const int qbase = blockIdx.x * 128;
    const int tid = threadIdx.x;
    const int warp = tid >> 5, lane = tid & 31;
    const int g = lane >> 3, lrow = lane & 7;

    // ---- stage Q (scaled by 1/8, hi/lo split): rows 0-63 in sK*, 64-127 in sV* ----
    {
        const float4* qr = (const float4*)(Q + (size_t)(b * SS + qbase + tid) * EE + h * DD);
        uint32_t* dh = (uint32_t*)((tid < 64 ? sKh : sVh) + (tid & 63) * LST);
        uint32_t* dl = (uint32_t*)((tid < 64 ? sKl : sVl) + (tid & 63) * LST);
        #pragma unroll
        for (int i = 0; i < 16; ++i) {
            float4 v = qr[i];
            v.x *= 0.125f; v.y *= 0.125f; v.z *= 0.125f; v.w *= 0.125f;
            uint32_t h0 = cvt2(v.x, v.y), h1 = cvt2(v.z, v.w);
            dh[2 * i] = h0; dh[2 * i + 1] = h1;
            dl[2 * i] = cvt2(v.x - lof(h0), v.y - hif(h0));
            dl[2 * i + 1] = cvt2(v.z - lof(h1), v.w - hif(h1));
        }
    }
    __syncthreads();

    // ---- load persistent Q A-fragments (hi/lo) ----
    uint32_t Qh[2][4][4], Ql[2][4][4];
    {
        const __nv_bfloat16* bh = (warp < 2) ? sKh : sVh;
        const __nv_bfloat16* bl = (warp < 2) ? sKl : sVl;
        const int rowbase = (warp & 1) * 32;
        const int arow = rowbase + (g & 1) * 8 + lrow;
        const int acol = (g >> 1) * 8;
        #pragma unroll
        for (int i = 0; i < 2; ++i)
            #pragma unroll
            for (int kb = 0; kb < 4; ++kb) {
                ldsm_x4(Qh[i][kb], smem_to_u32(bh + (arow + i * 16) * LST + acol + kb * 16));
                ldsm_x4(Ql[i][kb], smem_to_u32(bl + (arow + i * 16) * LST + acol + kb * 16));
            }
    }
    __syncthreads();

    float Oa[2][8][4];
    #pragma unroll
    for (int i = 0; i < 2; ++i)
        #pragma unroll
        for (int j = 0; j < 8; ++j)
            #pragma unroll
            for (int r = 0; r < 4; ++r) Oa[i][j][r] = 0.f;
    float lsum[4] = {0.f, 0.f, 0.f, 0.f};

    const uint32_t kOff = (uint32_t)(((g >> 1) * 8 + lrow) * LST + (g & 1) * 8) * 2;
    const uint32_t vOff = (uint32_t)(((g & 1) * 8 + lrow) * LST + (g >> 1) * 8) * 2;
    const uint32_t uKh = smem_to_u32(sKh), uKl = smem_to_u32(sKl);
    const uint32_t uVh = smem_to_u32(sVh), uVl = smem_to_u32(sVl);

    const float* kbase = K + (((size_t)b * SS) * HH + h) * DD;
    const float* vbase = V + (((size_t)b * SS) * HH + h) * DD;
    const ull* mrow = mbits + (size_t)(b * SS + qbase + warp * 32) * (SS / 64);

    const int srow = tid >> 1;
    const int sd0 = (tid & 1) * 32;

    #pragma unroll 1
    for (int t = 0; t < SS / 64; ++t) {
        const int kt = t * 64;
        __syncthreads();
        // ---- stage K/V tile as bf16 hi/lo ----
        {
            const float4* kr = (const float4*)(kbase + (size_t)(kt + srow) * (HH * DD) + sd0);
            const float4* vr = (const float4*)(vbase + (size_t)(kt + srow) * (HH * DD) + sd0);
            uint32_t* kh = (uint32_t*)(sKh + srow * LST + sd0);
            uint32_t* kl = (uint32_t*)(sKl + srow * LST + sd0);
            uint32_t* vh = (uint32_t*)(sVh + srow * LST + sd0);
            uint32_t* vl = (uint32_t*)(sVl + srow * LST + sd0);
            #pragma unroll
            for (int i = 0; i < 8; ++i) {
                float4 a = kr[i];
                uint32_t h0 = cvt2(a.x, a.y), h1 = cvt2(a.z, a.w);
                kh[2 * i] = h0; kh[2 * i + 1] = h1;
                kl[2 * i] = cvt2(a.x - lof(h0), a.y - hif(h0));
                kl[2 * i + 1] = cvt2(a.z - lof(h1), a.w - hif(h1));
                float4 c = vr[i];
                uint32_t g0 = cvt2(c.x, c.y), g1 = cvt2(c.z, c.w);
                vh[2 * i] = g0; vh[2 * i + 1] = g1;
                vl[2 * i] = cvt2(c.x - lof(g0), c.y - hif(g0));
                vl[2 * i + 1] = cvt2(c.z - lof(g1), c.w - hif(g1));
            }
        }
        __syncthreads();

        // ---- S = Q K^T (3-term split, term-major ordering) ----
        float S[2][8][4];
        #pragma unroll
        for (int i = 0; i < 2; ++i)
            #pragma unroll
            for (int j = 0; j < 8; ++j)
                #pragma unroll
                for (int r = 0; r < 4; ++r) S[i][j][r] = 0.f;

        #pragma unroll
        for (int np = 0; np < 4; ++np) {
            #pragma unroll
            for (int kb = 0; kb < 4; ++kb) {
                uint32_t Bh[4], Bl[4];
                uint32_t off = (uint32_t)(np * 16 * LST + kb * 16) * 2;
                ldsm_x4(Bh, uKh + off + kOff);
                ldsm_x4(Bl, uKl + off + kOff);
                #pragma unroll
                for (int i = 0; i < 2; ++i) mma_bf16(S[i][2 * np], Qh[i][kb], Bh[0], Bh[1]);
                #pragma unroll
                for (int i = 0; i < 2; ++i) mma_bf16(S[i][2 * np + 1], Qh[i][kb], Bh[2], Bh[3]);
                #pragma unroll
                for (int i = 0; i < 2; ++i) mma_bf16(S[i][2 * np], Qh[i][kb], Bl[0], Bl[1]);
                #pragma unroll
                for (int i = 0; i < 2; ++i) mma_bf16(S[i][2 * np + 1], Qh[i][kb], Bl[2], Bl[3]);
                #pragma unroll
                for (int i = 0; i < 2; ++i) mma_bf16(S[i][2 * np], Ql[i][kb], Bh[0], Bh[1]);
                #pragma unroll
                for (int i = 0; i < 2; ++i) mma_bf16(S[i][2 * np + 1], Ql[i][kb], Bh[2], Bh[3]);
            }
        }

        // ---- softmax (no max pass; masked -> 0) + pack P A-frags hi/lo ----
        uint32_t Ph[2][4][4], Pl[2][4][4];
        #pragma unroll
        for (int i = 0; i < 2; ++i) {
            ull mw0 = mrow[(size_t)(i * 16 + (lane >> 2)) * (SS / 64) + t];
            ull mw1 = mrow[(size_t)(i * 16 + 8 + (lane >> 2)) * (SS / 64) + t];
            #pragma unroll
            for (int nb = 0; nb < 8; ++nb) {
                int p0 = nb * 8 + (lane & 3) * 2;
                float e0 = ((mw0 >> p0) & 1ull) ? 0.f : __expf(S[i][nb][0]);
                float e1 = ((mw0 >> (p0 + 1)) & 1ull) ? 0.f : __expf(S[i][nb][1]);
                float e2 = ((mw1 >> p0) & 1ull) ? 0.f : __expf(S[i][nb][2]);
                float e3 = ((mw1 >> (p0 + 1)) & 1ull) ? 0.f : __expf(S[i][nb][3]);
                lsum[i * 2] += e0 + e1;
                lsum[i * 2 + 1] += e2 + e3;
                int kb = nb >> 1, sub = (nb & 1) * 2;
                uint32_t h01 = cvt2(e0, e1), h23 = cvt2(e2, e3);
                Ph[i][kb][sub] = h01;
                Ph[i][kb][sub + 1] = h23;
                Pl[i][kb][sub] = cvt2(e0 - lof(h01), e1 - hif(h01));
                Pl[i][kb][sub + 1] = cvt2(e2 - lof(h23), e3 - hif(h23));
            }
        }

        // ---- O += P V (3-term split, term-major), V frags via ldmatrix.trans ----
        #pragma unroll
        for (int dp = 0; dp < 4; ++dp) {
            #pragma unroll
            for (int kb = 0; kb < 4; ++kb) {
                uint32_t Bh[4], Bl[4];
                uint32_t off = (uint32_t)(kb * 16 * LST + dp * 16) * 2;
                ldsm_x4_t(Bh, uVh + off + vOff);
                ldsm_x4_t(Bl, uVl + off + vOff);
                #pragma unroll
                for (int i = 0; i < 2; ++i) mma_bf16(Oa[i][2 * dp], Ph[i][kb], Bh[0], Bh[1]);
                #pragma unroll
                for (int i = 0; i < 2; ++i) mma_bf16(Oa[i][2 * dp + 1], Ph[i][kb], Bh[2], Bh[3]);
                #pragma unroll
                for (int i = 0; i < 2; ++i) mma_bf16(Oa[i][2 * dp], Ph[i][kb], Bl[0], Bl[1]);
                #pragma unroll
                for (int i = 0; i < 2; ++i) mma_bf16(Oa[i][2 * dp + 1], Ph[i][kb], Bl[2], Bl[3]);
                #pragma unroll
                for (int i = 0; i < 2; ++i) mma_bf16(Oa[i][2 * dp], Pl[i][kb], Bh[0], Bh[1]);
                #pragma unroll
                for (int i = 0; i < 2; ++i) mma_bf16(Oa[i][2 * dp + 1], Pl[i][kb], Bh[2], Bh[3]);
            }
        }
    }

    // ---- normalize + store ----
    #pragma unroll
    for (int i = 0; i < 4; ++i) {
        lsum[i] += __shfl_xor_sync(0xffffffffu, lsum[i], 1);
        lsum[i] += __shfl_xor_sync(0xffffffffu, lsum[i], 2);
    }
    #pragma unroll
    for (int i = 0; i < 2; ++i) {
        float inv0 = 1.f / lsum[i * 2];
        float inv1 = 1.f / lsum[i * 2 + 1];
        int r0 = qbase + warp * 32 + i * 16 + (lane >> 2);
        float* o0 = O + (size_t)(b * SS + r0) * EE + h * DD;
        float* o1 = o0 + (size_t)8 * EE;
        #pragma unroll
        for (int nb = 0; nb < 8; ++nb) {
            int d = nb * 8 + (lane & 3) * 2;
            *(float2*)(o0 + d) = make_float2(Oa[i][nb][0] * inv0, Oa[i][nb][1] * inv0);
            *(float2*)(o1 + d) = make_float2(Oa[i][nb][2] * inv1, Oa[i][nb][3] * inv1);
        }
    }
}

// ---------------- launch ----------------
extern "C" void kernel_launch(void* const* d_in, const int* in_sizes, int n_in,
                              void* d_out, int out_size)
{
    const float* inputs = (const float*)d_in[0];
    const float* keys = (const float*)d_in[1];
    const float* values = (const float*)d_in[2];
    const float* wq = (const float*)d_in[3];
    const float* wo = (const float*)d_in[4];
    const void* mask_raw = d_in[5];
    float* out = (float*)d_out;

    float* qbuf; float* aobuf; ull* mbits;
    cudaGetSymbolAddress((void**)&qbuf, g_Q);
    cudaGetSymbolAddress((void**)&aobuf, g_AO);
    cudaGetSymbolAddress((void**)&mbits, g_maskBits);

    detect_mask_kernel<<<1, 256>>>((const unsigned int*)mask_raw);
    bitpack_mask_kernel<<<(BB * SS * SS / 64) / 256, 256>>>(mask_raw);

    dim3 ggrid(32, 8);
    gemm_mma_kernel<<<ggrid, 128>>>(inputs, wq, qbuf);
    attn_mma_kernel<<<dim3(SS / 128, HH, BB), 128>>>(keys, values, mbits, qbuf, aobuf);
    gemm_mma_kernel<<<ggrid, 128>>>(aobuf, wo, out);
}